// round 8
// baseline (speedup 1.0000x reference)
#include <cuda_runtime.h>
#include <cstdint>

#define NQ 32
#define NS 25
#define NL 64
#define NF 256
#define NH 64
#define NT (NQ * NS * 2)     // 1600 (q, s, i-half) tiles
#define XSP 260              // proj xs row stride (pad 4)

// Scratch (allocation-free rule: __device__ globals)
__device__ float g_WqT[NQ * NH * NL];      // per q: [h][i]
__device__ float g_WhT[NS * NH * NL];      // per s: [h][j]
__device__ float2 g_att2[(size_t)NT * 64 * 32];  // [T][j][32 i] duplicated pairs (~26MB)
__device__ unsigned g_flag[NT];

typedef unsigned long long u64;

__device__ __forceinline__ float fast_ex2(float x) {
    float r; asm("ex2.approx.f32 %0, %1;" : "=f"(r) : "f"(x)); return r;
}
__device__ __forceinline__ float fast_rcp(float x) {
    float r; asm("rcp.approx.f32 %0, %1;" : "=f"(r) : "f"(x)); return r;
}
__device__ __forceinline__ float fast_tanh(float x) {
    float r; asm("tanh.approx.f32 %0, %1;" : "=f"(r) : "f"(x)); return r;
}
__device__ __forceinline__ u64 f2fma(u64 a, u64 b, u64 c) {
    u64 r; asm("fma.rn.f32x2 %0, %1, %2, %3;" : "=l"(r) : "l"(a), "l"(b), "l"(c)); return r;
}

#define LOG2E 1.4426950408889634f

// K1: projection + flag reset. One block per (sequence b, l-quarter).
// dst[h][l] = sum_f x[l][f] * W[h][f] + bias[h], h-major in gmem.
__global__ __launch_bounds__(256) void k_project(const float* __restrict__ qs,
                                                 const float* __restrict__ hs,
                                                 const float* __restrict__ W,
                                                 const float* __restrict__ bias) {
    __shared__ float xs[16 * XSP];        // 16 rows x 256 (+pad)
    const int b  = blockIdx.x >> 2;
    const int lq = blockIdx.x & 3;
    const int t  = threadIdx.x;

    // reset tile flags (58368 threads total cover NT=1600)
    const int gt = blockIdx.x * 256 + t;
    if (gt < NT) g_flag[gt] = 0u;

    const float* x = ((b < NQ) ? (qs + (size_t)b * NL * NF)
                               : (hs + (size_t)(b - NQ) * NL * NF))
                     + (size_t)lq * 16 * NF;
    float* dst = (b < NQ) ? (g_WqT + (size_t)b * NH * NL)
                          : (g_WhT + (size_t)(b - NQ) * NH * NL);

    for (int e = t; e < 16 * NF / 4; e += 256) {
        int row = e >> 6;
        int c4 = (e & 63) * 4;
        *reinterpret_cast<float4*>(&xs[row * XSP + c4]) =
            *reinterpret_cast<const float4*>(&x[row * NF + c4]);
    }
    __syncthreads();

    const int h0 = 4 * (t >> 4);   // W loads broadcast across 16 lanes
    const int lr = t & 15;
    float acc[4] = {0.f, 0.f, 0.f, 0.f};

    #pragma unroll 2
    for (int f = 0; f < NF; f += 4) {
        float4 xv = *reinterpret_cast<const float4*>(&xs[lr * XSP + f]);
        #pragma unroll
        for (int c = 0; c < 4; c++) {
            float4 w = __ldg(reinterpret_cast<const float4*>(&W[(size_t)(h0 + c) * NF + f]));
            acc[c] = fmaf(w.x, xv.x, fmaf(w.y, xv.y, fmaf(w.z, xv.z, fmaf(w.w, xv.w, acc[c]))));
        }
    }
    const int l = lq * 16 + lr;
    #pragma unroll
    for (int c = 0; c < 4; c++)
        dst[(h0 + c) * NL + l] = acc[c] + __ldg(&bias[h0 + c]);
}

// K2: producer/consumer mega-kernel.
//   bid < NT:   scores+softmax for tile T=bid -> g_att2, then release g_flag[T]
//   bid >= NT:  AV for tile T=bid-NT, spins on g_flag[T] (producer has earlier bid
//               => already dispatched => no deadlock)
__global__ __launch_bounds__(256) void k_main(const float* __restrict__ hs,
                                              float* __restrict__ out) {
    extern __shared__ float sm[];
    const int bid = blockIdx.x;
    const int t = threadIdx.x;

    if (bid < NT) {
        // ---------------- scores + softmax ----------------
        const int T = bid;
        const int q = T / (2 * NS);
        const int sb = T % (2 * NS);
        const int s = sb >> 1;
        const int half = sb & 1;

        float* wqh = sm;             // [NH][32]
        float* whT = sm + 2048;      // [NH][64]
        {
            const float4* bsrc = reinterpret_cast<const float4*>(g_WhT + (size_t)s * NH * NL);
            float4* w2 = reinterpret_cast<float4*>(whT);
            for (int e = t; e < NH * NL / 4; e += 256) w2[e] = bsrc[e];
            const float* aq = g_WqT + (size_t)q * NH * NL + half * 32;
            for (int e = t; e < NH * 32 / 4; e += 256) {
                int h = e >> 3;
                int ii = (e & 7) * 4;
                *reinterpret_cast<float4*>(&wqh[h * 32 + ii]) =
                    *reinterpret_cast<const float4*>(&aq[h * NL + ii]);
            }
        }
        __syncthreads();

        const int i0a = 2 * (t >> 4);   // local query row in [0,32)
        const int j0 = 4 * (t & 15);    // support col in [0,64)

        float acc[2][4];
        #pragma unroll
        for (int r = 0; r < 2; r++)
            #pragma unroll
            for (int c = 0; c < 4; c++) acc[r][c] = 0.f;

        #pragma unroll 4
        for (int h = 0; h < NH; h++) {
            float2 a2 = *reinterpret_cast<const float2*>(&wqh[h * 32 + i0a]);
            float4 b4 = *reinterpret_cast<const float4*>(&whT[h * NL + j0]);
            acc[0][0] += fast_tanh(a2.x * b4.x);
            acc[0][1] += fast_tanh(a2.x * b4.y);
            acc[0][2] += fast_tanh(a2.x * b4.z);
            acc[0][3] += fast_tanh(a2.x * b4.w);
            acc[1][0] += fast_tanh(a2.y * b4.x);
            acc[1][1] += fast_tanh(a2.y * b4.y);
            acc[1][2] += fast_tanh(a2.y * b4.z);
            acc[1][3] += fast_tanh(a2.y * b4.w);
        }

        // softmax over j per row (64 j of a row live in one 16-lane group)
        float inv[2];
        #pragma unroll
        for (int r = 0; r < 2; r++) {
            float m = fmaxf(fmaxf(acc[r][0], acc[r][1]), fmaxf(acc[r][2], acc[r][3]));
            #pragma unroll
            for (int d = 1; d < 16; d <<= 1)
                m = fmaxf(m, __shfl_xor_sync(0xffffffffu, m, d));
            float e0 = fast_ex2((acc[r][0] - m) * LOG2E);
            float e1 = fast_ex2((acc[r][1] - m) * LOG2E);
            float e2 = fast_ex2((acc[r][2] - m) * LOG2E);
            float e3 = fast_ex2((acc[r][3] - m) * LOG2E);
            acc[r][0] = e0; acc[r][1] = e1; acc[r][2] = e2; acc[r][3] = e3;
            float ssum = (e0 + e1) + (e2 + e3);
            #pragma unroll
            for (int d = 1; d < 16; d <<= 1)
                ssum += __shfl_xor_sync(0xffffffffu, ssum, d);
            inv[r] = fast_rcp(ssum);
        }

        // store att transposed + duplicated: att2[T][j][i] = (v, v)
        float2* ad = g_att2 + (size_t)T * 2048;
        #pragma unroll
        for (int c = 0; c < 4; c++) {
            #pragma unroll
            for (int r = 0; r < 2; r++) {
                float v = acc[r][c] * inv[r];
                ad[(j0 + c) * 32 + (i0a + r)] = make_float2(v, v);
            }
        }

        __threadfence();
        __syncthreads();
        if (t == 0) {
            unsigned* fp = &g_flag[T];
            asm volatile("st.release.gpu.u32 [%0], %1;" :: "l"(fp), "r"(1u) : "memory");
        }
    } else {
        // ---------------- AV: out[i][f] = sum_j att[i][j] * hs[j][f] ----------------
        const int T = bid - NT;
        const int q = T / (2 * NS);
        const int sb = T % (2 * NS);
        const int s = sb >> 1;
        const int half = sb & 1;

        if (t == 0) {
            const unsigned* fp = &g_flag[T];
            unsigned v;
            do {
                asm volatile("ld.acquire.gpu.u32 %0, [%1];" : "=r"(v) : "l"(fp) : "memory");
                if (!v) __nanosleep(64);
            } while (!v);
        }
        __syncthreads();

        const int w = t >> 5, lane = t & 31;
        const int g = (w & 3) * 8;              // local i-group base [0,32)
        const int fb = (w >> 2) * 128 + lane * 4;  // f column [0,256)

        const float2* ap = g_att2 + (size_t)T * 2048 + g;   // + j*32 per row
        const float* hp = hs + (size_t)s * NL * NF + fb;    // + j*NF per row

        u64 o[8][2];
        #pragma unroll
        for (int r = 0; r < 8; r++) { o[r][0] = 0ull; o[r][1] = 0ull; }

        #pragma unroll 4
        for (int j = 0; j < NL; j++) {
            const ulonglong2* ab = reinterpret_cast<const ulonglong2*>(ap + (size_t)j * 32);
            ulonglong2 a01 = __ldg(ab);      // att rows g+0, g+1 (dup u64 each)
            ulonglong2 a23 = __ldg(ab + 1);
            ulonglong2 a45 = __ldg(ab + 2);
            ulonglong2 a67 = __ldg(ab + 3);
            ulonglong2 hv = __ldg(reinterpret_cast<const ulonglong2*>(hp + (size_t)j * NF));
            o[0][0] = f2fma(a01.x, hv.x, o[0][0]); o[0][1] = f2fma(a01.x, hv.y, o[0][1]);
            o[1][0] = f2fma(a01.y, hv.x, o[1][0]); o[1][1] = f2fma(a01.y, hv.y, o[1][1]);
            o[2][0] = f2fma(a23.x, hv.x, o[2][0]); o[2][1] = f2fma(a23.x, hv.y, o[2][1]);
            o[3][0] = f2fma(a23.y, hv.x, o[3][0]); o[3][1] = f2fma(a23.y, hv.y, o[3][1]);
            o[4][0] = f2fma(a45.x, hv.x, o[4][0]); o[4][1] = f2fma(a45.x, hv.y, o[4][1]);
            o[5][0] = f2fma(a45.y, hv.x, o[5][0]); o[5][1] = f2fma(a45.y, hv.y, o[5][1]);
            o[6][0] = f2fma(a67.x, hv.x, o[6][0]); o[6][1] = f2fma(a67.x, hv.y, o[6][1]);
            o[7][0] = f2fma(a67.y, hv.x, o[7][0]); o[7][1] = f2fma(a67.y, hv.y, o[7][1]);
        }

        float* op = out + (size_t)((q * NS + s) * NL + half * 32 + g) * NF + fb;
        #pragma unroll
        for (int r = 0; r < 8; r++) {
            ulonglong2 v; v.x = o[r][0]; v.y = o[r][1];
            *reinterpret_cast<ulonglong2*>(op + (size_t)r * NF) = v;
        }
    }
}

extern "C" void kernel_launch(void* const* d_in, const int* in_sizes, int n_in,
                              void* d_out, int out_size) {
    const float* qs = (const float*)d_in[0];
    const float* hs = (const float*)d_in[1];
    const float* W  = (const float*)d_in[2];
    const float* b  = (const float*)d_in[3];
    float* out = (float*)d_out;

    const int smem_main = 6144 * (int)sizeof(float);  // 24 KB (scores buffers)
    cudaFuncSetAttribute(k_main, cudaFuncAttributeMaxDynamicSharedMemorySize, smem_main);

    k_project<<<(NQ + NS) * 4, 256>>>(qs, hs, W, b);
    k_main<<<2 * NT, 256, smem_main>>>(hs, out);
}

// round 9
// speedup vs baseline: 1.5871x; 1.5871x over previous
#include <cuda_runtime.h>
#include <cstdint>

#define NQ 32
#define NS 25
#define NL 64
#define NF 256
#define NH 64
#define NT (NQ * NS * 2)     // 1600 (q, s, i-half) tiles
#define XSP 260              // proj xs row stride (pad 4)
#define ATS2 34              // attT2 row stride in float2 units

// Scratch (allocation-free rule: __device__ globals)
__device__ float g_WqT[NQ * NH * NL];  // per q: [h][i]
__device__ float g_WhT[NS * NH * NL];  // per s: [h][j]
__device__ unsigned g_ticket;

typedef unsigned long long u64;

__device__ __forceinline__ float fast_ex2(float x) {
    float r; asm("ex2.approx.f32 %0, %1;" : "=f"(r) : "f"(x)); return r;
}
__device__ __forceinline__ float fast_rcp(float x) {
    float r; asm("rcp.approx.f32 %0, %1;" : "=f"(r) : "f"(x)); return r;
}
__device__ __forceinline__ float fast_tanh(float x) {
    float r; asm("tanh.approx.f32 %0, %1;" : "=f"(r) : "f"(x)); return r;
}
__device__ __forceinline__ u64 f2fma(u64 a, u64 b, u64 c) {
    u64 r; asm("fma.rn.f32x2 %0, %1, %2, %3;" : "=l"(r) : "l"(a), "l"(b), "l"(c)); return r;
}

#define LOG2E 1.4426950408889634f

// K1: projection (+ ticket reset for the persistent k_attn).
// One block per (sequence b, l-quarter).
// dst[h][l] = sum_f x[l][f] * W[h][f] + bias[h], h-major in gmem.
__global__ __launch_bounds__(256) void k_project(const float* __restrict__ qs,
                                                 const float* __restrict__ hs,
                                                 const float* __restrict__ W,
                                                 const float* __restrict__ bias) {
    __shared__ float xs[16 * XSP];        // 16 rows x 256 (+pad)
    const int b  = blockIdx.x >> 2;
    const int lq = blockIdx.x & 3;
    const int t  = threadIdx.x;

    if (blockIdx.x == 0 && t == 0) g_ticket = 0u;  // visible to k_attn (kernel order)

    const float* x = ((b < NQ) ? (qs + (size_t)b * NL * NF)
                               : (hs + (size_t)(b - NQ) * NL * NF))
                     + (size_t)lq * 16 * NF;
    float* dst = (b < NQ) ? (g_WqT + (size_t)b * NH * NL)
                          : (g_WhT + (size_t)(b - NQ) * NH * NL);

    for (int e = t; e < 16 * NF / 4; e += 256) {
        int row = e >> 6;
        int c4 = (e & 63) * 4;
        *reinterpret_cast<float4*>(&xs[row * XSP + c4]) =
            *reinterpret_cast<const float4*>(&x[row * NF + c4]);
    }
    __syncthreads();

    const int h0 = 4 * (t >> 4);   // W loads broadcast across 16 lanes
    const int lr = t & 15;
    float acc[4] = {0.f, 0.f, 0.f, 0.f};

    #pragma unroll 2
    for (int f = 0; f < NF; f += 4) {
        float4 xv = *reinterpret_cast<const float4*>(&xs[lr * XSP + f]);
        #pragma unroll
        for (int c = 0; c < 4; c++) {
            float4 w = __ldg(reinterpret_cast<const float4*>(&W[(size_t)(h0 + c) * NF + f]));
            acc[c] = fmaf(w.x, xv.x, fmaf(w.y, xv.y, fmaf(w.z, xv.z, fmaf(w.w, xv.w, acc[c]))));
        }
    }
    const int l = lq * 16 + lr;
    #pragma unroll
    for (int c = 0; c < 4; c++)
        dst[(h0 + c) * NL + l] = acc[c] + __ldg(&bias[h0 + c]);
}

// K2: persistent fused kernel. 592 CTAs (one wave at occ 4) loop over 1600
// (q, s, i-half) tiles via an atomic ticket. Per tile: scores (tanh.approx,
// MUFU-bound) -> softmax -> att@hs (FMA/LDS-bound). Co-resident CTAs desync
// across tiles, overlapping the MUFU phase of one with the FMA phase of another.
// smem (floats): wqh[0..2048)=[NH][32]; whT[2048..6144)=[NH][64]
//   overlay: attT2[0..4352)=[NL][ATS2] float2; hsq[4352..12544)=[NL][128]
//   ticket broadcast slot at [12544]. Total 12548 f = 50192 B -> occ 4.
__global__ __launch_bounds__(256) void k_attn(const float* __restrict__ hs,
                                              float* __restrict__ out) {
    extern __shared__ float sm[];
    float* wqh = sm;                                   // [NH][32]
    float* whT = sm + 2048;                            // [NH][64]
    float2* attT2 = reinterpret_cast<float2*>(sm);     // [NL][ATS2]
    float* hsq = sm + 4352;                            // [NL][128]
    float* tslot = sm + 12544;

    const int t = threadIdx.x;

    for (;;) {
        if (t == 0) tslot[0] = __uint_as_float(atomicAdd(&g_ticket, 1u));
        __syncthreads();
        const unsigned T = __float_as_uint(tslot[0]);
        if (T >= NT) return;

        const int q = T / (2 * NS);
        const int sb = T % (2 * NS);
        const int s = sb >> 1;
        const int half = sb & 1;

        {
            const float4* bsrc = reinterpret_cast<const float4*>(g_WhT + (size_t)s * NH * NL);
            float4* w2 = reinterpret_cast<float4*>(whT);
            for (int e = t; e < NH * NL / 4; e += 256) w2[e] = bsrc[e];
            const float* aq = g_WqT + (size_t)q * NH * NL + half * 32;
            for (int e = t; e < NH * 32 / 4; e += 256) {
                int h = e >> 3;
                int ii = (e & 7) * 4;
                *reinterpret_cast<float4*>(&wqh[h * 32 + ii]) =
                    *reinterpret_cast<const float4*>(&aq[h * NL + ii]);
            }
        }
        __syncthreads();

        const int i0a = 2 * (t >> 4);   // local query row in [0,32) (broadcast loads)
        const int j0 = 4 * (t & 15);    // support col in [0,64) (coalesced loads)

        // Phase A: acc[r][c] = sum_h tanh(wq[i0a+r][h] * wh[j0+c][h])
        float acc[2][4];
        #pragma unroll
        for (int r = 0; r < 2; r++)
            #pragma unroll
            for (int c = 0; c < 4; c++) acc[r][c] = 0.f;

        #pragma unroll 4
        for (int h = 0; h < NH; h++) {
            float2 a2 = *reinterpret_cast<const float2*>(&wqh[h * 32 + i0a]);
            float4 b4 = *reinterpret_cast<const float4*>(&whT[h * NL + j0]);
            acc[0][0] += fast_tanh(a2.x * b4.x);
            acc[0][1] += fast_tanh(a2.x * b4.y);
            acc[0][2] += fast_tanh(a2.x * b4.z);
            acc[0][3] += fast_tanh(a2.x * b4.w);
            acc[1][0] += fast_tanh(a2.y * b4.x);
            acc[1][1] += fast_tanh(a2.y * b4.y);
            acc[1][2] += fast_tanh(a2.y * b4.z);
            acc[1][3] += fast_tanh(a2.y * b4.w);
        }

        // Phase B: softmax over j per row (64 j of a row live in one 16-lane group).
        float inv[2];
        #pragma unroll
        for (int r = 0; r < 2; r++) {
            float m = fmaxf(fmaxf(acc[r][0], acc[r][1]), fmaxf(acc[r][2], acc[r][3]));
            #pragma unroll
            for (int d = 1; d < 16; d <<= 1)
                m = fmaxf(m, __shfl_xor_sync(0xffffffffu, m, d));
            float e0 = fast_ex2((acc[r][0] - m) * LOG2E);
            float e1 = fast_ex2((acc[r][1] - m) * LOG2E);
            float e2 = fast_ex2((acc[r][2] - m) * LOG2E);
            float e3 = fast_ex2((acc[r][3] - m) * LOG2E);
            acc[r][0] = e0; acc[r][1] = e1; acc[r][2] = e2; acc[r][3] = e3;
            float ssum = (e0 + e1) + (e2 + e3);
            #pragma unroll
            for (int d = 1; d < 16; d <<= 1)
                ssum += __shfl_xor_sync(0xffffffffu, ssum, d);
            inv[r] = fast_rcp(ssum);
        }

        __syncthreads();  // all phase-A smem reads done before overlay writes

        // Store att transposed + duplicated: attT2[j][i] = (v, v)
        #pragma unroll
        for (int c = 0; c < 4; c++) {
            #pragma unroll
            for (int r = 0; r < 2; r++) {
                float v = acc[r][c] * inv[r];
                attT2[(j0 + c) * ATS2 + (i0a + r)] = make_float2(v, v);
            }
        }

        // Phase C: out[i][f] = sum_j att[i][j] * hs[j][f], 2 f-half passes.
        const float* hg = hs + (size_t)s * NL * NF;
        float* op = out + (size_t)((q * NS + s) * NL + half * 32) * NF;
        const int i0c = 4 * (t >> 5);   // warp-uniform: att loads broadcast
        const int fb = 4 * (t & 31);    // [0,128)

        #pragma unroll
        for (int p = 0; p < 2; p++) {
            for (int e = t; e < NL * 128 / 4; e += 256) {
                int j = e >> 5;
                int f4 = (e & 31) * 4;
                *reinterpret_cast<float4*>(&hsq[j * 128 + f4]) =
                    __ldg(reinterpret_cast<const float4*>(&hg[(size_t)j * NF + 128 * p + f4]));
            }
            __syncthreads();   // attT2 stores (p==0) + hsq staged

            u64 o[4][2];
            #pragma unroll
            for (int r = 0; r < 4; r++) { o[r][0] = 0ull; o[r][1] = 0ull; }

            #pragma unroll 4
            for (int j = 0; j < NL; j++) {
                ulonglong2 a01 = *reinterpret_cast<const ulonglong2*>(&attT2[j * ATS2 + i0c]);
                ulonglong2 a23 = *reinterpret_cast<const ulonglong2*>(&attT2[j * ATS2 + i0c + 2]);
                ulonglong2 hv = *reinterpret_cast<const ulonglong2*>(&hsq[j * 128 + fb]);
                o[0][0] = f2fma(a01.x, hv.x, o[0][0]); o[0][1] = f2fma(a01.x, hv.y, o[0][1]);
                o[1][0] = f2fma(a01.y, hv.x, o[1][0]); o[1][1] = f2fma(a01.y, hv.y, o[1][1]);
                o[2][0] = f2fma(a23.x, hv.x, o[2][0]); o[2][1] = f2fma(a23.x, hv.y, o[2][1]);
                o[3][0] = f2fma(a23.y, hv.x, o[3][0]); o[3][1] = f2fma(a23.y, hv.y, o[3][1]);
            }
            #pragma unroll
            for (int r = 0; r < 4; r++) {
                ulonglong2 v; v.x = o[r][0]; v.y = o[r][1];
                *reinterpret_cast<ulonglong2*>(&op[(size_t)(i0c + r) * NF + 128 * p + fb]) = v;
            }
            __syncthreads();   // reads done before smem reuse (next pass / next tile)
        }
    }
}

extern "C" void kernel_launch(void* const* d_in, const int* in_sizes, int n_in,
                              void* d_out, int out_size) {
    const float* qs = (const float*)d_in[0];
    const float* hs = (const float*)d_in[1];
    const float* W  = (const float*)d_in[2];
    const float* b  = (const float*)d_in[3];
    float* out = (float*)d_out;

    const int smem_attn = 12548 * (int)sizeof(float);  // 50192 B -> occ 4
    cudaFuncSetAttribute(k_attn, cudaFuncAttributeMaxDynamicSharedMemorySize, smem_attn);

    k_project<<<(NQ + NS) * 4, 256>>>(qs, hs, W, b);
    k_attn<<<148 * 4, 256, smem_attn>>>(hs, out);
}

// round 10
// speedup vs baseline: 1.7133x; 1.0796x over previous
#include <cuda_runtime.h>
#include <cstdint>

#define NQ 32
#define NS 25
#define NL 64
#define NF 256
#define NH 64
#define NT (NQ * NS)         // 800 (q, s) tiles
#define XSP 260              // proj xs row stride (pad 4)
#define ATS 68               // attT row stride (floats; mult of 4)

// Scratch (allocation-free rule: __device__ globals)
__device__ float g_WqT[NQ * NH * NL];  // per q: [h][i]
__device__ float g_WhT[NS * NH * NL];  // per s: [h][j]
__device__ unsigned g_ticket;

typedef unsigned long long u64;

__device__ __forceinline__ float fast_ex2(float x) {
    float r; asm("ex2.approx.f32 %0, %1;" : "=f"(r) : "f"(x)); return r;
}
__device__ __forceinline__ float fast_rcp(float x) {
    float r; asm("rcp.approx.f32 %0, %1;" : "=f"(r) : "f"(x)); return r;
}
__device__ __forceinline__ float fast_tanh(float x) {
    float r; asm("tanh.approx.f32 %0, %1;" : "=f"(r) : "f"(x)); return r;
}
__device__ __forceinline__ u64 f2fma(u64 a, u64 b, u64 c) {
    u64 r; asm("fma.rn.f32x2 %0, %1, %2, %3;" : "=l"(r) : "l"(a), "l"(b), "l"(c)); return r;
}
__device__ __forceinline__ u64 dup2(float x) {
    u64 r; asm("mov.b64 %0, {%1, %1};" : "=l"(r) : "f"(x)); return r;
}

#define LOG2E 1.4426950408889634f

// K1: projection (+ ticket reset for persistent k_attn).
// One block per (sequence b, l-quarter).
__global__ __launch_bounds__(256) void k_project(const float* __restrict__ qs,
                                                 const float* __restrict__ hs,
                                                 const float* __restrict__ W,
                                                 const float* __restrict__ bias) {
    __shared__ float xs[16 * XSP];
    const int b  = blockIdx.x >> 2;
    const int lq = blockIdx.x & 3;
    const int t  = threadIdx.x;

    if (blockIdx.x == 0 && t == 0) g_ticket = 0u;  // visible to k_attn (kernel order)

    const float* x = ((b < NQ) ? (qs + (size_t)b * NL * NF)
                               : (hs + (size_t)(b - NQ) * NL * NF))
                     + (size_t)lq * 16 * NF;
    float* dst = (b < NQ) ? (g_WqT + (size_t)b * NH * NL)
                          : (g_WhT + (size_t)(b - NQ) * NH * NL);

    for (int e = t; e < 16 * NF / 4; e += 256) {
        int row = e >> 6;
        int c4 = (e & 63) * 4;
        *reinterpret_cast<float4*>(&xs[row * XSP + c4]) =
            *reinterpret_cast<const float4*>(&x[row * NF + c4]);
    }
    __syncthreads();

    const int h0 = 4 * (t >> 4);   // W loads broadcast across 16 lanes
    const int lr = t & 15;
    float acc[4] = {0.f, 0.f, 0.f, 0.f};

    #pragma unroll 2
    for (int f = 0; f < NF; f += 4) {
        float4 xv = *reinterpret_cast<const float4*>(&xs[lr * XSP + f]);
        #pragma unroll
        for (int c = 0; c < 4; c++) {
            float4 w = __ldg(reinterpret_cast<const float4*>(&W[(size_t)(h0 + c) * NF + f]));
            acc[c] = fmaf(w.x, xv.x, fmaf(w.y, xv.y, fmaf(w.z, xv.z, fmaf(w.w, xv.w, acc[c]))));
        }
    }
    const int l = lq * 16 + lr;
    #pragma unroll
    for (int c = 0; c < 4; c++)
        dst[(h0 + c) * NL + l] = acc[c] + __ldg(&bias[h0 + c]);
}

// K2: persistent fused kernel over 800 (q, s) tiles.
// smem (floats): phase A: wqT[0..4096)=[NH][64]; whT[4096..8192)=[NH][64]
//   overlay:     attT[0..4352)=[64 j][ATS] (plain floats, [j][i])
//                hsq[4352..12544)=[NL][128] f-half of hs[s]
//   ticket slot at [12544]. Total 12548 f = 50192 B -> occ 4.
__global__ __launch_bounds__(256) void k_attn(const float* __restrict__ hs,
                                              float* __restrict__ out) {
    extern __shared__ float sm[];
    float* wqT = sm;             // [NH][64]
    float* whT = sm + 4096;      // [NH][64]
    float* attT = sm;            // overlay: [j][i], stride ATS
    float* hsq = sm + 4352;      // overlay: [NL][128]
    float* tslot = sm + 12544;

    const int t = threadIdx.x;

    for (;;) {
        if (t == 0) tslot[0] = __uint_as_float(atomicAdd(&g_ticket, 1u));
        __syncthreads();
        const unsigned T = __float_as_uint(tslot[0]);
        if (T >= NT) return;

        const int q = T / NS;
        const int s = T % NS;

        {
            const float4* a4 = reinterpret_cast<const float4*>(g_WqT + (size_t)q * NH * NL);
            const float4* b4 = reinterpret_cast<const float4*>(g_WhT + (size_t)s * NH * NL);
            float4* w1 = reinterpret_cast<float4*>(wqT);
            float4* w2 = reinterpret_cast<float4*>(whT);
            for (int e = t; e < NH * NL / 4; e += 256) { w1[e] = a4[e]; w2[e] = b4[e]; }
        }
        __syncthreads();

        const int i0 = 4 * (t >> 4);   // query rows (broadcast loads)
        const int j0 = 4 * (t & 15);   // support cols (coalesced loads)

        // Phase A: acc[r][c] = sum_h tanh(wq[i0+r][h] * wh[j0+c][h])
        float acc[4][4];
        #pragma unroll
        for (int r = 0; r < 4; r++)
            #pragma unroll
            for (int c = 0; c < 4; c++) acc[r][c] = 0.f;

        #pragma unroll 2
        for (int h = 0; h < NH; h++) {
            float4 a4 = *reinterpret_cast<const float4*>(&wqT[h * NL + i0]);
            float4 b4 = *reinterpret_cast<const float4*>(&whT[h * NL + j0]);
            float av[4] = {a4.x, a4.y, a4.z, a4.w};
            float bv[4] = {b4.x, b4.y, b4.z, b4.w};
            #pragma unroll
            for (int r = 0; r < 4; r++)
                #pragma unroll
                for (int c = 0; c < 4; c++)
                    acc[r][c] += fast_tanh(av[r] * bv[c]);
        }

        // Phase B: softmax over j per row (64 j of a row live in one 16-lane group).
        float inv[4];
        #pragma unroll
        for (int r = 0; r < 4; r++) {
            float m = fmaxf(fmaxf(acc[r][0], acc[r][1]), fmaxf(acc[r][2], acc[r][3]));
            #pragma unroll
            for (int d = 1; d < 16; d <<= 1)
                m = fmaxf(m, __shfl_xor_sync(0xffffffffu, m, d));
            float e0 = fast_ex2((acc[r][0] - m) * LOG2E);
            float e1 = fast_ex2((acc[r][1] - m) * LOG2E);
            float e2 = fast_ex2((acc[r][2] - m) * LOG2E);
            float e3 = fast_ex2((acc[r][3] - m) * LOG2E);
            acc[r][0] = e0; acc[r][1] = e1; acc[r][2] = e2; acc[r][3] = e3;
            float ssum = (e0 + e1) + (e2 + e3);
            #pragma unroll
            for (int d = 1; d < 16; d <<= 1)
                ssum += __shfl_xor_sync(0xffffffffu, ssum, d);
            inv[r] = fast_rcp(ssum);
        }

        __syncthreads();  // all phase-A smem reads done before overlay writes

        // Store att transposed: attT[j][i] (STS.128 over i per c).
        #pragma unroll
        for (int c = 0; c < 4; c++) {
            float4 v = make_float4(acc[0][c] * inv[0], acc[1][c] * inv[1],
                                   acc[2][c] * inv[2], acc[3][c] * inv[3]);
            *reinterpret_cast<float4*>(&attT[(j0 + c) * ATS + i0]) = v;
        }

        // Phase C: out[i][f] = sum_j att[i][j] * hs[j][f], 2 f-half passes.
        // Warp w owns i-rows [8w, 8w+8); lanes span 128 f (4 each).
        const float* hg = hs + (size_t)s * NL * NF;
        float* op = out + (size_t)((q * NS + s) * NL) * NF;
        const int w = t >> 5;
        const int ib = 8 * w;            // warp-uniform: att loads broadcast
        const int fb = 4 * (t & 31);     // [0,128)

        #pragma unroll
        for (int p = 0; p < 2; p++) {
            for (int e = t; e < NL * 128 / 4; e += 256) {
                int j = e >> 5;
                int f4 = (e & 31) * 4;
                *reinterpret_cast<float4*>(&hsq[j * 128 + f4]) =
                    __ldg(reinterpret_cast<const float4*>(&hg[(size_t)j * NF + 128 * p + f4]));
            }
            __syncthreads();   // attT stores (p==0) + hsq staged

            u64 o[8][2];
            #pragma unroll
            for (int r = 0; r < 8; r++) { o[r][0] = 0ull; o[r][1] = 0ull; }

            #pragma unroll 4
            for (int j = 0; j < NL; j++) {
                float4 al = *reinterpret_cast<const float4*>(&attT[j * ATS + ib]);      // rows 0-3
                float4 ah = *reinterpret_cast<const float4*>(&attT[j * ATS + ib + 4]);  // rows 4-7
                ulonglong2 hv = *reinterpret_cast<const ulonglong2*>(&hsq[j * 128 + fb]);
                u64 d0 = dup2(al.x), d1 = dup2(al.y), d2 = dup2(al.z), d3 = dup2(al.w);
                u64 d4 = dup2(ah.x), d5 = dup2(ah.y), d6 = dup2(ah.z), d7 = dup2(ah.w);
                o[0][0] = f2fma(d0, hv.x, o[0][0]); o[0][1] = f2fma(d0, hv.y, o[0][1]);
                o[1][0] = f2fma(d1, hv.x, o[1][0]); o[1][1] = f2fma(d1, hv.y, o[1][1]);
                o[2][0] = f2fma(d2, hv.x, o[2][0]); o[2][1] = f2fma(d2, hv.y, o[2][1]);
                o[3][0] = f2fma(d3, hv.x, o[3][0]); o[3][1] = f2fma(d3, hv.y, o[3][1]);
                o[4][0] = f2fma(d4, hv.x, o[4][0]); o[4][1] = f2fma(d4, hv.y, o[4][1]);
                o[5][0] = f2fma(d5, hv.x, o[5][0]); o[5][1] = f2fma(d5, hv.y, o[5][1]);
                o[6][0] = f2fma(d6, hv.x, o[6][0]); o[6][1] = f2fma(d6, hv.y, o[6][1]);
                o[7][0] = f2fma(d7, hv.x, o[7][0]); o[7][1] = f2fma(d7, hv.y, o[7][1]);
            }
            #pragma unroll
            for (int r = 0; r < 8; r++) {
                ulonglong2 v; v.x = o[r][0]; v.y = o[r][1];
                *reinterpret_cast<ulonglong2*>(&op[(size_t)(ib + r) * NF + 128 * p + fb]) = v;
            }
            __syncthreads();   // reads done before smem reuse (next pass / next tile)
        }
    }
}

extern "C" void kernel_launch(void* const* d_in, const int* in_sizes, int n_in,
                              void* d_out, int out_size) {
    const float* qs = (const float*)d_in[0];
    const float* hs = (const float*)d_in[1];
    const float* W  = (const float*)d_in[2];
    const float* b  = (const float*)d_in[3];
    float* out = (float*)d_out;

    const int smem_attn = 12548 * (int)sizeof(float);  // 50192 B -> occ 4
    cudaFuncSetAttribute(k_attn, cudaFuncAttributeMaxDynamicSharedMemorySize, smem_attn);

    k_project<<<(NQ + NS) * 4, 256>>>(qs, hs, W, b);
    k_attn<<<148 * 4, 256, smem_attn>>>(hs, out);
}